// round 16
// baseline (speedup 1.0000x reference)
#include <cuda_runtime.h>
#include <math.h>

// ---------------------------------------------------------------------------
// InvariantPolynomial: out = SILU_CST * sum_e x_left[oi[e]] * x_right[e] * f(|pos_e|)
// R15 lesson: ticket finalize is fine (tid0-only fence) but 8-edge unroll +
// finalize pushed regs to 58 -> occ 43%. R16: 4-edge loop + pair-table +
// __launch_bounds__(256,8) (<=32 regs, occ ~88%), ticket finalize kept.
// ---------------------------------------------------------------------------

#define TABLE_N  4096                // intervals; pair i covers [i, i+1]
#define D_MAX    5.25f               // all 20 gaussian emb underflow in fp32 for d >= ~4.8
#define QH       (24.0f / 8192.0f)   // quadrature step (exactly representable)
#define TBLB     65                  // (TABLE_N+1)*4 lanes -> 65 blocks of 256
#define NQBK     32                  // 32*256 = 8192 quad pts (+ endpoint)
#define MAXMB    8192

__device__ float2   g_tab2[TABLE_N]; // (f[i], f[i+1])
__device__ float    g_qpart[NQBK + 1];
__device__ double   g_mpart[MAXMB];
__device__ unsigned g_done;          // monotone across graph replays

__device__ __forceinline__ float silu_f(float p) {
    return __fdividef(p, 1.0f + __expf(-p));
}

// ---------------------------------------------------------------------------
// Setup: identical to R11 (proven fast).
// ---------------------------------------------------------------------------
__global__ void __launch_bounds__(256) setup_kernel(const float* __restrict__ W1,
                                                    const float* __restrict__ W2) {
    const int tid = threadIdx.x;
    if (blockIdx.x < TBLB) {
        __shared__ float sW1[600];
        __shared__ float sW2s[32];
        for (int i = tid; i < 600; i += 256) sW1[i] = W1[i];
        if (tid < 32) {
            float s = 0.f;
            if (tid < 30) {
                #pragma unroll
                for (int c = 0; c < 5; c++) s += W2[tid * 5 + c];
            }
            sW2s[tid] = s * 0.18257418583505536f;   // 1/sqrt(30)
        }
        __syncthreads();

        int gt  = blockIdx.x * 256 + tid;
        int i   = gt >> 2;                          // table entry 0..TABLE_N
        int sub = gt & 3;                           // j-chunk (8 hidden units)
        if (i > TABLE_N) return;
        float d = (float)i * (D_MAX / (float)TABLE_N);

        float e[20];
        #pragma unroll
        for (int k = 0; k < 20; k++) {
            float vk   = (float)(k + 1) * (3.5f / 21.0f);
            float diff = (d - vk) * (21.0f / 3.5f);
            e[k] = __expf(-diff * diff) * (1.0f / 1.12f);
        }

        int j0 = sub * 8;                           // 0,8,16,24 (30,31 pad=0)
        float pre[8];
        #pragma unroll
        for (int j = 0; j < 8; j++) pre[j] = 0.f;
        #pragma unroll
        for (int k = 0; k < 20; k++) {
            #pragma unroll
            for (int j = 0; j < 8; j++) {
                int jj = j0 + j;
                float wv = (jj < 30) ? sW1[k * 30 + jj] : 0.f;
                pre[j] = fmaf(e[k], wv, pre[j]);
            }
        }
        float f = 0.f;
        #pragma unroll
        for (int j = 0; j < 8; j++) {
            float p = pre[j] * 0.22360679774997896f;   // 1/sqrt(20)
            f = fmaf(silu_f(p), sW2s[j0 + j], f);
        }
        f += __shfl_xor_sync(0xffffffffu, f, 1);       // reduce 4 lanes
        f += __shfl_xor_sync(0xffffffffu, f, 2);
        if (sub == 0) {
            float* base = (float*)g_tab2;
            if (i < TABLE_N) base[2 * i] = f;          // pair i .x
            if (i >= 1)      base[2 * (i - 1) + 1] = f;// pair i-1 .y
        }
        return;
    }

    // ---- trapezoid quadrature for silu normalize2mom ----
    __shared__ float sred[256];
    int   i = (blockIdx.x - TBLB) * 256 + tid;      // 0..8191
    float z   = fmaf((float)i, QH, -12.0f);
    float s   = silu_f(z);
    float phi = 0.3989422804014327f * __expf(-0.5f * z * z);
    float v   = s * s * phi;
    if (i == 0) v *= 0.5f;                          // left endpoint weight
    sred[tid] = v;
    __syncthreads();
    #pragma unroll
    for (int st = 128; st > 0; st >>= 1) {
        if (tid < st) sred[tid] += sred[tid + st];
        __syncthreads();
    }
    if (tid == 0) g_qpart[blockIdx.x - TBLB] = sred[0];
    if (blockIdx.x == TBLB && tid == 1) {           // right endpoint z = +12
        float s2   = silu_f(12.0f);
        float phi2 = 0.3989422804014327f * __expf(-0.5f * 144.0f);
        g_qpart[NQBK] = 0.5f * s2 * s2 * phi2;
    }
}

// ---------------------------------------------------------------------------
// Main pass: 4 edges/thread (32-reg proven), pair-table LDG.64, grid-stride,
// lightweight tid0-only ticket finalize.
// ---------------------------------------------------------------------------
__device__ __forceinline__ float quad_term(float4 a, float4 b, float4 c,
                                           float4 w, int4 id,
                                           const float* __restrict__ xleft) {
    float d0 = sqrtf(fmaf(a.x, a.x, fmaf(a.y, a.y, a.z * a.z)));
    float d1 = sqrtf(fmaf(a.w, a.w, fmaf(b.x, b.x, b.y * b.y)));
    float d2 = sqrtf(fmaf(b.z, b.z, fmaf(b.w, b.w, c.x * c.x)));
    float d3 = sqrtf(fmaf(c.y, c.y, fmaf(c.z, c.z, c.w * c.w)));

    const float sc = (float)TABLE_N / D_MAX;
    float t0 = fminf(d0 * sc, (float)TABLE_N - 0.5f);
    float t1 = fminf(d1 * sc, (float)TABLE_N - 0.5f);
    float t2 = fminf(d2 * sc, (float)TABLE_N - 0.5f);
    float t3 = fminf(d3 * sc, (float)TABLE_N - 0.5f);
    int i0 = (int)t0, i1 = (int)t1, i2 = (int)t2, i3 = (int)t3;

    float g0 = __ldg(&xleft[id.x]);
    float g1 = __ldg(&xleft[id.y]);
    float g2 = __ldg(&xleft[id.z]);
    float g3 = __ldg(&xleft[id.w]);

    float2 p0 = __ldg(&g_tab2[i0]);
    float2 p1 = __ldg(&g_tab2[i1]);
    float2 p2 = __ldg(&g_tab2[i2]);
    float2 p3 = __ldg(&g_tab2[i3]);

    float f0 = fmaf(t0 - (float)i0, p0.y - p0.x, p0.x);
    float f1 = fmaf(t1 - (float)i1, p1.y - p1.x, p1.x);
    float f2 = fmaf(t2 - (float)i2, p2.y - p2.x, p2.x);
    float f3 = fmaf(t3 - (float)i3, p3.y - p3.x, p3.x);

    return f0 * w.x * g0 + f1 * w.y * g1 + f2 * w.z * g2 + f3 * w.w * g3;
}

__device__ __forceinline__ float edge_term1(float x, float y, float z,
                                            float w, int id,
                                            const float* __restrict__ xleft) {
    float d  = sqrtf(fmaf(x, x, fmaf(y, y, z * z)));
    float ft = fminf(d * ((float)TABLE_N / D_MAX), (float)TABLE_N - 0.5f);
    int   i  = (int)ft;
    float2 p = __ldg(&g_tab2[i]);
    float  f = fmaf(ft - (float)i, p.y - p.x, p.x);
    return f * w * __ldg(&xleft[id]);
}

__global__ void __launch_bounds__(256, 8)
main_kernel(const float4* __restrict__ pos4,
            const float4* __restrict__ xr4,
            const int4*   __restrict__ idx4,
            const float*  __restrict__ xleft,
            const float*  __restrict__ pos,
            const float*  __restrict__ xr,
            const int*    __restrict__ idx,
            float* __restrict__ out,
            int n4, int E, int nb) {
    const int tid = threadIdx.x;
    float local = 0.f;
    for (int t = blockIdx.x * 256 + tid; t < n4; t += nb * 256) {
        float4 a = pos4[3 * t];
        float4 b = pos4[3 * t + 1];
        float4 c = pos4[3 * t + 2];
        float4 w = xr4[t];
        int4  id = idx4[t];
        local += quad_term(a, b, c, w, id, xleft);
    }
    if (blockIdx.x == 0 && tid == 0) {              // tail edges (E % 4)
        for (int e2 = n4 * 4; e2 < E; e2++)
            local += edge_term1(pos[3 * e2], pos[3 * e2 + 1], pos[3 * e2 + 2],
                                xr[e2], idx[e2], xleft);
    }

    // block reduction -> one double partial per block
    #pragma unroll
    for (int o = 16; o > 0; o >>= 1)
        local += __shfl_down_sync(0xffffffffu, local, o);
    __shared__ float warpsum[8];
    int lane = tid & 31, wid = tid >> 5;
    if (lane == 0) warpsum[wid] = local;
    __syncthreads();

    __shared__ unsigned last_s;
    if (tid == 0) {
        float v = warpsum[0];
        #pragma unroll
        for (int k = 1; k < 8; k++) v += warpsum[k];
        g_mpart[blockIdx.x] = (double)v;            // tid0's own write...
        __threadfence();                            // ...released by tid0 only
        unsigned tk = atomicAdd(&g_done, 1u);       // monotone across replays
        last_s = ((tk % (unsigned)nb) == (unsigned)(nb - 1)) ? 1u : 0u;
    }
    __syncthreads();
    if (!last_s) return;

    // ---- last-arriving block finalizes (runs once; spills OK) ----
    __threadfence();                                // acquire (one block only)
    __shared__ double redm[256], redq[256];
    double m = 0.0, q = 0.0;
    for (int i = tid; i < nb; i += 256) m += ((volatile double*)g_mpart)[i];
    for (int i = tid; i <= NQBK; i += 256) q += (double)((volatile float*)g_qpart)[i];
    redm[tid] = m;
    redq[tid] = q;
    __syncthreads();
    #pragma unroll
    for (int s = 128; s > 0; s >>= 1) {
        if (tid < s) { redm[tid] += redm[tid + s]; redq[tid] += redq[tid + s]; }
        __syncthreads();
    }
    if (tid == 0) {
        double integral = (double)QH * redq[0];
        double cst = 1.0 / sqrt(integral);          // ~1.679 silu normalize2mom
        out[0] = (float)(redm[0] * cst);
    }
}

// ---------------------------------------------------------------------------
extern "C" void kernel_launch(void* const* d_in, const int* in_sizes, int n_in,
                              void* d_out, int out_size) {
    const float* pos = (const float*)d_in[0];   // [E,3]
    const float* xr  = (const float*)d_in[1];   // [E,1]
    const float* xl  = (const float*)d_in[2];   // [N,1]
    const float* W1  = (const float*)d_in[3];   // [20,30]
    const float* W2  = (const float*)d_in[4];   // [30,5]
    const int*   oi  = (const int*)d_in[5];     // [E]

    int E = in_sizes[1];
    if (E < 0) E = 0;
    int n4 = E / 4;

    setup_kernel<<<TBLB + NQBK, 256>>>(W1, W2);

    int nb = (n4 + 255) / 256;
    if (nb < 1) nb = 1;
    if (nb > MAXMB) nb = MAXMB;
    main_kernel<<<nb, 256>>>((const float4*)pos, (const float4*)xr,
                             (const int4*)oi, xl, pos, xr, oi,
                             (float*)d_out, n4, E, nb);
}

// round 17
// speedup vs baseline: 1.1943x; 1.1943x over previous
#include <cuda_runtime.h>
#include <math.h>

// ---------------------------------------------------------------------------
// InvariantPolynomial: out = SILU_CST * sum_e x_left[oi[e]] * x_right[e] * f(|pos_e|)
// FINAL (revert to R11, best measured 23.1us):
//  - sh[:, :1] == 1 (l=0) -> SH dead code; answer = scalar reduction
//  - f(d) built per-launch as a 4096-interval float2 pair table (one LDG.64
//    per edge); setup parallelized 4 lanes/entry; quadrature for SILU_CST
//    replicated on-device (fp32 trapezoid, 8193 pts)
//  - main: 8 edges/thread, per-block double partial (deterministic)
//  - separate tiny final kernel (fused-finalize variants all measured slower)
// ---------------------------------------------------------------------------

#define TABLE_N  4096                // intervals; pair i covers [i, i+1]
#define D_MAX    5.25f               // all 20 gaussian emb underflow in fp32 for d >= ~4.8
#define QH       (24.0f / 8192.0f)   // quadrature step (exactly representable)
#define TBLB     65                  // (TABLE_N+1)*4 lanes -> 65 blocks
#define NQBK     32                  // 32*256 = 8192 quad pts (+ endpoint)
#define MAXMB    8192

__device__ float2 g_tab2[TABLE_N];   // (f[i], f[i+1])
__device__ float  g_qpart[NQBK + 1];
__device__ double g_mpart[MAXMB];

__device__ __forceinline__ float silu_f(float p) {
    return __fdividef(p, 1.0f + __expf(-p));
}

// ---------------------------------------------------------------------------
// Setup: blocks [0,TBLB) table entries (4 lanes/entry); then quadrature.
// ---------------------------------------------------------------------------
__global__ void __launch_bounds__(256) setup_kernel(const float* __restrict__ W1,
                                                    const float* __restrict__ W2) {
    const int tid = threadIdx.x;
    if (blockIdx.x < TBLB) {
        __shared__ float sW1[600];
        __shared__ float sW2s[32];
        for (int i = tid; i < 600; i += 256) sW1[i] = W1[i];
        if (tid < 32) {
            float s = 0.f;
            if (tid < 30) {
                #pragma unroll
                for (int c = 0; c < 5; c++) s += W2[tid * 5 + c];
            }
            sW2s[tid] = s * 0.18257418583505536f;   // 1/sqrt(30)
        }
        __syncthreads();

        int gt  = blockIdx.x * 256 + tid;
        int i   = gt >> 2;                          // table entry 0..TABLE_N
        int sub = gt & 3;
        if (i > TABLE_N) return;
        float d = (float)i * (D_MAX / (float)TABLE_N);

        float e[20];
        #pragma unroll
        for (int k = 0; k < 20; k++) {
            float vk   = (float)(k + 1) * (3.5f / 21.0f);
            float diff = (d - vk) * (21.0f / 3.5f);
            e[k] = __expf(-diff * diff) * (1.0f / 1.12f);
        }

        int j0 = sub * 8;
        float pre[8];
        #pragma unroll
        for (int j = 0; j < 8; j++) pre[j] = 0.f;
        #pragma unroll
        for (int k = 0; k < 20; k++) {
            #pragma unroll
            for (int j = 0; j < 8; j++) {
                int jj = j0 + j;
                float wv = (jj < 30) ? sW1[k * 30 + jj] : 0.f;
                pre[j] = fmaf(e[k], wv, pre[j]);
            }
        }
        float f = 0.f;
        #pragma unroll
        for (int j = 0; j < 8; j++) {
            float p = pre[j] * 0.22360679774997896f;   // 1/sqrt(20)
            f = fmaf(silu_f(p), sW2s[j0 + j], f);
        }
        f += __shfl_xor_sync(0xffffffffu, f, 1);
        f += __shfl_xor_sync(0xffffffffu, f, 2);
        if (sub == 0) {
            float* base = (float*)g_tab2;
            if (i < TABLE_N) base[2 * i] = f;
            if (i >= 1)      base[2 * (i - 1) + 1] = f;
        }
        return;
    }

    __shared__ float sred[256];
    int   i = (blockIdx.x - TBLB) * 256 + tid;
    float z   = fmaf((float)i, QH, -12.0f);
    float s   = silu_f(z);
    float phi = 0.3989422804014327f * __expf(-0.5f * z * z);
    float v   = s * s * phi;
    if (i == 0) v *= 0.5f;
    sred[tid] = v;
    __syncthreads();
    #pragma unroll
    for (int st = 128; st > 0; st >>= 1) {
        if (tid < st) sred[tid] += sred[tid + st];
        __syncthreads();
    }
    if (tid == 0) g_qpart[blockIdx.x - TBLB] = sred[0];
    if (blockIdx.x == TBLB && tid == 1) {
        float s2   = silu_f(12.0f);
        float phi2 = 0.3989422804014327f * __expf(-0.5f * 144.0f);
        g_qpart[NQBK] = 0.5f * s2 * s2 * phi2;
    }
}

// ---------------------------------------------------------------------------
// Main pass: 8 edges/thread -> 2 independent gather chains, loads front-batched.
// ---------------------------------------------------------------------------
__device__ __forceinline__ float quad_term(float4 a, float4 b, float4 c,
                                           float4 w, int4 id,
                                           const float* __restrict__ xleft) {
    float d0 = sqrtf(fmaf(a.x, a.x, fmaf(a.y, a.y, a.z * a.z)));
    float d1 = sqrtf(fmaf(a.w, a.w, fmaf(b.x, b.x, b.y * b.y)));
    float d2 = sqrtf(fmaf(b.z, b.z, fmaf(b.w, b.w, c.x * c.x)));
    float d3 = sqrtf(fmaf(c.y, c.y, fmaf(c.z, c.z, c.w * c.w)));

    const float sc = (float)TABLE_N / D_MAX;
    float t0 = fminf(d0 * sc, (float)TABLE_N - 0.5f);
    float t1 = fminf(d1 * sc, (float)TABLE_N - 0.5f);
    float t2 = fminf(d2 * sc, (float)TABLE_N - 0.5f);
    float t3 = fminf(d3 * sc, (float)TABLE_N - 0.5f);
    int i0 = (int)t0, i1 = (int)t1, i2 = (int)t2, i3 = (int)t3;

    float g0 = __ldg(&xleft[id.x]);
    float g1 = __ldg(&xleft[id.y]);
    float g2 = __ldg(&xleft[id.z]);
    float g3 = __ldg(&xleft[id.w]);

    float2 p0 = __ldg(&g_tab2[i0]);
    float2 p1 = __ldg(&g_tab2[i1]);
    float2 p2 = __ldg(&g_tab2[i2]);
    float2 p3 = __ldg(&g_tab2[i3]);

    float f0 = fmaf(t0 - (float)i0, p0.y - p0.x, p0.x);
    float f1 = fmaf(t1 - (float)i1, p1.y - p1.x, p1.x);
    float f2 = fmaf(t2 - (float)i2, p2.y - p2.x, p2.x);
    float f3 = fmaf(t3 - (float)i3, p3.y - p3.x, p3.x);

    return f0 * w.x * g0 + f1 * w.y * g1 + f2 * w.z * g2 + f3 * w.w * g3;
}

__device__ __forceinline__ float edge_term1(float x, float y, float z,
                                            float w, int id,
                                            const float* __restrict__ xleft) {
    float d  = sqrtf(fmaf(x, x, fmaf(y, y, z * z)));
    float ft = fminf(d * ((float)TABLE_N / D_MAX), (float)TABLE_N - 0.5f);
    int   i  = (int)ft;
    float2 p = __ldg(&g_tab2[i]);
    float  f = fmaf(ft - (float)i, p.y - p.x, p.x);
    return f * w * __ldg(&xleft[id]);
}

__global__ void __launch_bounds__(256)
main_kernel(const float4* __restrict__ pos4,
            const float4* __restrict__ xr4,
            const int4*   __restrict__ idx4,
            const float*  __restrict__ xleft,
            const float*  __restrict__ pos,
            const float*  __restrict__ xr,
            const int*    __restrict__ idx,
            int n8, int E) {
    float local = 0.f;
    for (int t = blockIdx.x * blockDim.x + threadIdx.x; t < n8;
         t += gridDim.x * blockDim.x) {
        float4 a0 = pos4[6 * t];
        float4 b0 = pos4[6 * t + 1];
        float4 c0 = pos4[6 * t + 2];
        float4 a1 = pos4[6 * t + 3];
        float4 b1 = pos4[6 * t + 4];
        float4 c1 = pos4[6 * t + 5];
        float4 w0 = xr4[2 * t];
        float4 w1 = xr4[2 * t + 1];
        int4  id0 = idx4[2 * t];
        int4  id1 = idx4[2 * t + 1];

        local += quad_term(a0, b0, c0, w0, id0, xleft);
        local += quad_term(a1, b1, c1, w1, id1, xleft);
    }
    if (blockIdx.x == 0 && threadIdx.x == 0) {      // tail edges (E % 8)
        for (int e2 = n8 * 8; e2 < E; e2++)
            local += edge_term1(pos[3 * e2], pos[3 * e2 + 1], pos[3 * e2 + 2],
                                xr[e2], idx[e2], xleft);
    }

    // block reduction -> one double partial per block
    #pragma unroll
    for (int o = 16; o > 0; o >>= 1)
        local += __shfl_down_sync(0xffffffffu, local, o);
    __shared__ float warpsum[8];
    int lane = threadIdx.x & 31, wid = threadIdx.x >> 5;
    if (lane == 0) warpsum[wid] = local;
    __syncthreads();
    if (wid == 0) {
        float v = (lane < 8) ? warpsum[lane] : 0.f;
        #pragma unroll
        for (int o = 4; o > 0; o >>= 1)
            v += __shfl_down_sync(0xffffffffu, v, o);
        if (lane == 0) g_mpart[blockIdx.x] = (double)v;
    }
}

// ---------------------------------------------------------------------------
__global__ void __launch_bounds__(256) final_kernel(float* __restrict__ out, int nmb) {
    __shared__ double redm[256], redq[256];
    double m = 0.0, q = 0.0;
    for (int i = threadIdx.x; i < nmb; i += 256) m += g_mpart[i];
    for (int i = threadIdx.x; i <= NQBK; i += 256) q += (double)g_qpart[i];
    redm[threadIdx.x] = m;
    redq[threadIdx.x] = q;
    __syncthreads();
    #pragma unroll
    for (int s = 128; s > 0; s >>= 1) {
        if (threadIdx.x < s) {
            redm[threadIdx.x] += redm[threadIdx.x + s];
            redq[threadIdx.x] += redq[threadIdx.x + s];
        }
        __syncthreads();
    }
    if (threadIdx.x == 0) {
        double integral = (double)QH * redq[0];
        double cst = 1.0 / sqrt(integral);          // ~1.679 silu normalize2mom
        out[0] = (float)(redm[0] * cst);
    }
}

// ---------------------------------------------------------------------------
extern "C" void kernel_launch(void* const* d_in, const int* in_sizes, int n_in,
                              void* d_out, int out_size) {
    const float* pos = (const float*)d_in[0];   // [E,3]
    const float* xr  = (const float*)d_in[1];   // [E,1]
    const float* xl  = (const float*)d_in[2];   // [N,1]
    const float* W1  = (const float*)d_in[3];   // [20,30]
    const float* W2  = (const float*)d_in[4];   // [30,5]
    const int*   oi  = (const int*)d_in[5];     // [E]

    int E = in_sizes[1];
    if (E < 0) E = 0;
    int n8 = E / 8;

    setup_kernel<<<TBLB + NQBK, 256>>>(W1, W2);

    int nb = (n8 + 255) / 256;
    if (nb < 1) nb = 1;
    if (nb > MAXMB) nb = MAXMB;
    main_kernel<<<nb, 256>>>((const float4*)pos, (const float4*)xr,
                             (const int4*)oi, xl, pos, xr, oi, n8, E);

    final_kernel<<<1, 256>>>((float*)d_out, nb);
}